// round 1
// baseline (speedup 1.0000x reference)
#include <cuda_runtime.h>
#include <cstdint>

// Problem constants
#define M_TOTAL 2400      // B*N queries
#define K_DIM   256       // HIDDEN
#define N_TOTAL 16384     // GROUPS*GDIM*GDIM
#define P_DIM   32
#define C_DIM   256

// GEMM1 tiling
#define BM 128
#define BN 128
#define BK 16
#define NKT (K_DIM / BK)  // 16
#define SA_STRIDE 20      // conflict-free for quad-row frag loads
#define SB_STRIDE 136

// 157 MB scratch for per-query dynamic weights w[2400][16384]
__device__ float g_w[(size_t)M_TOTAL * N_TOTAL];

__device__ __forceinline__ uint32_t f2tf32(float f) {
    uint32_t u;
    asm("cvt.rna.tf32.f32 %0, %1;" : "=r"(u) : "f"(f));
    return u;
}

__device__ __forceinline__ void mma_tf32(float (&d)[4], const uint32_t (&a)[4],
                                         const uint32_t (&b)[2]) {
    asm volatile(
        "mma.sync.aligned.m16n8k8.row.col.f32.tf32.tf32.f32 "
        "{%0,%1,%2,%3}, {%4,%5,%6,%7}, {%8,%9}, {%0,%1,%2,%3};"
        : "+f"(d[0]), "+f"(d[1]), "+f"(d[2]), "+f"(d[3])
        : "r"(a[0]), "r"(a[1]), "r"(a[2]), "r"(a[3]), "r"(b[0]), "r"(b[1]));
}

__device__ __forceinline__ void cp16(uint32_t saddr, const void* gaddr) {
    asm volatile("cp.async.cg.shared.global [%0], [%1], 16;" ::"r"(saddr), "l"(gaddr));
}

// ---------------------------------------------------------------------------
// Kernel A: w = qc @ W_gen + b_gen   ([2400,256] x [256,16384])
// 256 threads = 8 warps (2 x 4). Per-warp 64x32 output via m16n8k8 tf32.
// ---------------------------------------------------------------------------
__global__ void __launch_bounds__(256)
gemm1_kernel(const float* __restrict__ qc, const float* __restrict__ Wg,
             const float* __restrict__ bg) {
    __shared__ float sA[2][BM][SA_STRIDE];
    __shared__ float sB[2][BK][SB_STRIDE];

    const int tid  = threadIdx.x;
    const int warp = tid >> 5, lane = tid & 31;
    const int wm = warp >> 2, wn = warp & 3;     // warp grid 2(m) x 4(n)
    const int gid = lane >> 2, tig = lane & 3;
    const int m0 = blockIdx.y * BM;
    const int n0 = blockIdx.x * BN;

    float acc[4][4][4];
#pragma unroll
    for (int i = 0; i < 4; i++)
#pragma unroll
        for (int j = 0; j < 4; j++)
#pragma unroll
            for (int k = 0; k < 4; k++) acc[i][j][k] = 0.f;

    // async tile loaders (512 x 16B chunks each, 2 per thread)
    auto load_stage = [&](int buf, int kt) {
#pragma unroll
        for (int i = 0; i < 2; i++) {
            int chunk = tid + 256 * i;
            // A: [128 rows][16 cols] of qc
            int ar = chunk >> 2, ac = (chunk & 3) * 4;
            int m = m0 + ar; if (m >= M_TOTAL) m = M_TOTAL - 1;  // clamp (dup rows)
            uint32_t sa = (uint32_t)__cvta_generic_to_shared(&sA[buf][ar][ac]);
            cp16(sa, qc + (size_t)m * K_DIM + kt * BK + ac);
            // B: [16 rows][128 cols] of W_gen
            int br = chunk >> 5, bc = (chunk & 31) * 4;
            uint32_t sb = (uint32_t)__cvta_generic_to_shared(&sB[buf][br][bc]);
            cp16(sb, Wg + (size_t)(kt * BK + br) * N_TOTAL + n0 + bc);
        }
    };

    load_stage(0, 0);
    asm volatile("cp.async.commit_group;" ::: "memory");

    for (int kt = 0; kt < NKT; kt++) {
        const int buf = kt & 1;
        if (kt + 1 < NKT) {
            load_stage(buf ^ 1, kt + 1);
            asm volatile("cp.async.commit_group;" ::: "memory");
            asm volatile("cp.async.wait_group 1;" ::: "memory");
        } else {
            asm volatile("cp.async.wait_group 0;" ::: "memory");
        }
        __syncthreads();

#pragma unroll
        for (int ks = 0; ks < 2; ks++) {  // two k8 steps per BK=16 tile
            uint32_t a[4][4], b[4][2];
#pragma unroll
            for (int mt = 0; mt < 4; mt++) {
                int r = wm * 64 + mt * 16 + gid;
                int c = ks * 8 + tig;
                a[mt][0] = f2tf32(sA[buf][r][c]);
                a[mt][1] = f2tf32(sA[buf][r + 8][c]);
                a[mt][2] = f2tf32(sA[buf][r][c + 4]);
                a[mt][3] = f2tf32(sA[buf][r + 8][c + 4]);
            }
#pragma unroll
            for (int nt = 0; nt < 4; nt++) {
                int kk = ks * 8 + tig;
                int n  = wn * 32 + nt * 8 + gid;
                b[nt][0] = f2tf32(sB[buf][kk][n]);
                b[nt][1] = f2tf32(sB[buf][kk + 4][n]);
            }
#pragma unroll
            for (int mt = 0; mt < 4; mt++)
#pragma unroll
                for (int nt = 0; nt < 4; nt++) mma_tf32(acc[mt][nt], a[mt], b[nt]);
        }
        __syncthreads();
    }

    // epilogue: add bias, store fp32 w
#pragma unroll
    for (int mt = 0; mt < 4; mt++) {
        int r = m0 + wm * 64 + mt * 16 + gid;
#pragma unroll
        for (int nt = 0; nt < 4; nt++) {
            int c = n0 + wn * 32 + nt * 8 + 2 * tig;
            float2 bb = *reinterpret_cast<const float2*>(bg + c);
            if (r < M_TOTAL) {
                float2 v = {acc[mt][nt][0] + bb.x, acc[mt][nt][1] + bb.y};
                *reinterpret_cast<float2*>(&g_w[(size_t)r * N_TOTAL + c]) = v;
            }
            if (r + 8 < M_TOTAL) {
                float2 v = {acc[mt][nt][2] + bb.x, acc[mt][nt][3] + bb.y};
                *reinterpret_cast<float2*>(&g_w[(size_t)(r + 8) * N_TOTAL + c]) = v;
            }
        }
    }
}

// ---------------------------------------------------------------------------
// Kernel B: per-query grouped mixing + LayerNorm + ReLU.
// 1 CTA per query (2400 CTAs), 128 threads = 4 warps, warp g handles group g:
//   mixed_g[32p x 64e] = X_g[32 x 64d] @ W_g^T[64d x 64e]   (tf32 mma)
// Fragments loaded straight from global (L1 merges sector halves).
// Then warp-per-8-rows LayerNorm over 256 channels from padded smem.
// ---------------------------------------------------------------------------
__global__ void __launch_bounds__(128)
mix_ln_kernel(const float* __restrict__ x, const float* __restrict__ gamma,
              const float* __restrict__ beta, float* __restrict__ out) {
    __shared__ float sMix[P_DIM][C_DIM + 1];  // stride 257: conflict-free col-strided reads

    const int q    = blockIdx.x;
    const int warp = threadIdx.x >> 5, lane = threadIdx.x & 31;
    const int gid = lane >> 2, tig = lane & 3;
    const int g = warp;

    const float* wg = g_w + (size_t)q * N_TOTAL + g * 4096;  // [e][d] 64x64
    const float* xq = x + (size_t)q * (P_DIM * C_DIM) + g * 64;

    float acc[2][8][4];
#pragma unroll
    for (int i = 0; i < 2; i++)
#pragma unroll
        for (int j = 0; j < 8; j++)
#pragma unroll
            for (int k = 0; k < 4; k++) acc[i][j][k] = 0.f;

#pragma unroll
    for (int ks = 0; ks < 8; ks++) {
        const int d0 = ks * 8 + tig;
        uint32_t a[2][4];
#pragma unroll
        for (int mt = 0; mt < 2; mt++) {
            int p = mt * 16 + gid;
            a[mt][0] = f2tf32(xq[p * C_DIM + d0]);
            a[mt][1] = f2tf32(xq[(p + 8) * C_DIM + d0]);
            a[mt][2] = f2tf32(xq[p * C_DIM + d0 + 4]);
            a[mt][3] = f2tf32(xq[(p + 8) * C_DIM + d0 + 4]);
        }
#pragma unroll
        for (int nt = 0; nt < 8; nt++) {
            int e = nt * 8 + gid;
            uint32_t b[2];
            b[0] = f2tf32(wg[e * 64 + d0]);
            b[1] = f2tf32(wg[e * 64 + d0 + 4]);
            mma_tf32(acc[0][nt], a[0], b);
            mma_tf32(acc[1][nt], a[1], b);
        }
    }

    // stash mixed tile in smem
#pragma unroll
    for (int mt = 0; mt < 2; mt++)
#pragma unroll
        for (int nt = 0; nt < 8; nt++) {
            int p = mt * 16 + gid;
            int c = g * 64 + nt * 8 + 2 * tig;
            sMix[p][c]     = acc[mt][nt][0];
            sMix[p][c + 1] = acc[mt][nt][1];
            sMix[p + 8][c]     = acc[mt][nt][2];
            sMix[p + 8][c + 1] = acc[mt][nt][3];
        }
    __syncthreads();

    // LayerNorm + ReLU: warp handles rows [warp*8, warp*8+8)
    float gm[8], bt[8];
#pragma unroll
    for (int j = 0; j < 8; j++) {
        int c = j * 32 + lane;
        gm[j] = gamma[c];
        bt[j] = beta[c];
    }
#pragma unroll
    for (int r = 0; r < 8; r++) {
        const int p = warp * 8 + r;
        float v[8], s = 0.f, s2 = 0.f;
#pragma unroll
        for (int j = 0; j < 8; j++) {
            v[j] = sMix[p][j * 32 + lane];
            s += v[j];
            s2 += v[j] * v[j];
        }
#pragma unroll
        for (int o = 16; o > 0; o >>= 1) {
            s  += __shfl_xor_sync(0xffffffffu, s, o);
            s2 += __shfl_xor_sync(0xffffffffu, s2, o);
        }
        const float mean = s * (1.f / 256.f);
        const float var  = s2 * (1.f / 256.f) - mean * mean;
        const float rs   = rsqrtf(var + 1e-5f);
        float* orow = out + (size_t)q * (P_DIM * C_DIM) + p * C_DIM;
#pragma unroll
        for (int j = 0; j < 8; j++) {
            float o = (v[j] - mean) * rs * gm[j] + bt[j];
            orow[j * 32 + lane] = fmaxf(o, 0.f);
        }
    }
}

// ---------------------------------------------------------------------------
extern "C" void kernel_launch(void* const* d_in, const int* in_sizes, int n_in,
                              void* d_out, int out_size) {
    const float* x     = (const float*)d_in[0];
    const float* qc    = (const float*)d_in[1];
    const float* Wg    = (const float*)d_in[2];
    const float* bg    = (const float*)d_in[3];
    const float* gamma = (const float*)d_in[4];
    const float* beta  = (const float*)d_in[5];
    float* out = (float*)d_out;

    dim3 gridA(N_TOTAL / BN, (M_TOTAL + BM - 1) / BM);  // 128 x 19
    gemm1_kernel<<<gridA, 256>>>(qc, Wg, bg);
    mix_ln_kernel<<<M_TOTAL, 128>>>(x, gamma, beta, out);
}

// round 2
// speedup vs baseline: 1.0148x; 1.0148x over previous
#include <cuda_runtime.h>
#include <cstdint>

// Problem constants
#define M_TOTAL 2400      // B*N queries
#define K_DIM   256       // HIDDEN
#define N_TOTAL 16384     // GROUPS*GDIM*GDIM
#define P_DIM   32
#define C_DIM   256

// GEMM1 tiling
#define BM 128
#define BN 128
#define BK 16
#define NKT (K_DIM / BK)  // 16
#define SA_STRIDE 20      // conflict-free for quad-row frag loads
#define SB_STRIDE 136

// 157 MB scratch for per-query dynamic weights w[2400][16384]
__device__ float g_w[(size_t)M_TOTAL * N_TOTAL];

__device__ __forceinline__ uint32_t f2tf32(float f) {
    uint32_t u;
    asm("cvt.rna.tf32.f32 %0, %1;" : "=r"(u) : "f"(f));
    return u;
}

__device__ __forceinline__ void mma_tf32(float (&d)[4], const uint32_t (&a)[4],
                                         const uint32_t (&b)[2]) {
    asm volatile(
        "mma.sync.aligned.m16n8k8.row.col.f32.tf32.tf32.f32 "
        "{%0,%1,%2,%3}, {%4,%5,%6,%7}, {%8,%9}, {%0,%1,%2,%3};"
        : "+f"(d[0]), "+f"(d[1]), "+f"(d[2]), "+f"(d[3])
        : "r"(a[0]), "r"(a[1]), "r"(a[2]), "r"(a[3]), "r"(b[0]), "r"(b[1]));
}

__device__ __forceinline__ void cp16(uint32_t saddr, const void* gaddr) {
    asm volatile("cp.async.cg.shared.global [%0], [%1], 16;" ::"r"(saddr), "l"(gaddr));
}

// ---------------------------------------------------------------------------
// Kernel A: w = qc @ W_gen + b_gen   ([2400,256] x [256,16384])
// 256 threads = 8 warps (2 x 4). Per-warp 64x32 output via m16n8k8 tf32.
// ---------------------------------------------------------------------------
__global__ void __launch_bounds__(256)
gemm1_kernel(const float* __restrict__ qc, const float* __restrict__ Wg,
             const float* __restrict__ bg) {
    __shared__ float sA[2][BM][SA_STRIDE];
    __shared__ float sB[2][BK][SB_STRIDE];

    const int tid  = threadIdx.x;
    const int warp = tid >> 5, lane = tid & 31;
    const int wm = warp >> 2, wn = warp & 3;     // warp grid 2(m) x 4(n)
    const int gid = lane >> 2, tig = lane & 3;
    const int m0 = blockIdx.y * BM;
    const int n0 = blockIdx.x * BN;

    float acc[4][4][4];
#pragma unroll
    for (int i = 0; i < 4; i++)
#pragma unroll
        for (int j = 0; j < 4; j++)
#pragma unroll
            for (int k = 0; k < 4; k++) acc[i][j][k] = 0.f;

    // async tile loaders (512 x 16B chunks each, 2 per thread)
    auto load_stage = [&](int buf, int kt) {
#pragma unroll
        for (int i = 0; i < 2; i++) {
            int chunk = tid + 256 * i;
            // A: [128 rows][16 cols] of qc
            int ar = chunk >> 2, ac = (chunk & 3) * 4;
            int m = m0 + ar; if (m >= M_TOTAL) m = M_TOTAL - 1;  // clamp (dup rows)
            uint32_t sa = (uint32_t)__cvta_generic_to_shared(&sA[buf][ar][ac]);
            cp16(sa, qc + (size_t)m * K_DIM + kt * BK + ac);
            // B: [16 rows][128 cols] of W_gen
            int br = chunk >> 5, bc = (chunk & 31) * 4;
            uint32_t sb = (uint32_t)__cvta_generic_to_shared(&sB[buf][br][bc]);
            cp16(sb, Wg + (size_t)(kt * BK + br) * N_TOTAL + n0 + bc);
        }
    };

    load_stage(0, 0);
    asm volatile("cp.async.commit_group;" ::: "memory");

    for (int kt = 0; kt < NKT; kt++) {
        const int buf = kt & 1;
        if (kt + 1 < NKT) {
            load_stage(buf ^ 1, kt + 1);
            asm volatile("cp.async.commit_group;" ::: "memory");
            asm volatile("cp.async.wait_group 1;" ::: "memory");
        } else {
            asm volatile("cp.async.wait_group 0;" ::: "memory");
        }
        __syncthreads();

#pragma unroll
        for (int ks = 0; ks < 2; ks++) {  // two k8 steps per BK=16 tile
            uint32_t a[4][4], b[4][2];
#pragma unroll
            for (int mt = 0; mt < 4; mt++) {
                int r = wm * 64 + mt * 16 + gid;
                int c = ks * 8 + tig;
                a[mt][0] = f2tf32(sA[buf][r][c]);
                a[mt][1] = f2tf32(sA[buf][r + 8][c]);
                a[mt][2] = f2tf32(sA[buf][r][c + 4]);
                a[mt][3] = f2tf32(sA[buf][r + 8][c + 4]);
            }
#pragma unroll
            for (int nt = 0; nt < 4; nt++) {
                int kk = ks * 8 + tig;
                int n  = wn * 32 + nt * 8 + gid;
                b[nt][0] = f2tf32(sB[buf][kk][n]);
                b[nt][1] = f2tf32(sB[buf][kk + 4][n]);
            }
#pragma unroll
            for (int mt = 0; mt < 4; mt++)
#pragma unroll
                for (int nt = 0; nt < 4; nt++) mma_tf32(acc[mt][nt], a[mt], b[nt]);
        }
        __syncthreads();
    }

    // epilogue: add bias, store fp32 w
#pragma unroll
    for (int mt = 0; mt < 4; mt++) {
        int r = m0 + wm * 64 + mt * 16 + gid;
#pragma unroll
        for (int nt = 0; nt < 4; nt++) {
            int c = n0 + wn * 32 + nt * 8 + 2 * tig;
            float2 bb = *reinterpret_cast<const float2*>(bg + c);
            if (r < M_TOTAL) {
                float2 v = {acc[mt][nt][0] + bb.x, acc[mt][nt][1] + bb.y};
                *reinterpret_cast<float2*>(&g_w[(size_t)r * N_TOTAL + c]) = v;
            }
            if (r + 8 < M_TOTAL) {
                float2 v = {acc[mt][nt][2] + bb.x, acc[mt][nt][3] + bb.y};
                *reinterpret_cast<float2*>(&g_w[(size_t)(r + 8) * N_TOTAL + c]) = v;
            }
        }
    }
}

// ---------------------------------------------------------------------------
// Kernel B: per-query grouped mixing + LayerNorm + ReLU.
// 1 CTA per query (2400 CTAs), 128 threads = 4 warps, warp g handles group g:
//   mixed_g[32p x 64e] = X_g[32 x 64d] @ W_g^T[64d x 64e]   (tf32 mma)
// Fragments loaded straight from global (L1 merges sector halves).
// Then warp-per-8-rows LayerNorm over 256 channels from padded smem.
// ---------------------------------------------------------------------------
__global__ void __launch_bounds__(128)
mix_ln_kernel(const float* __restrict__ x, const float* __restrict__ gamma,
              const float* __restrict__ beta, float* __restrict__ out) {
    __shared__ float sMix[P_DIM][C_DIM + 1];  // stride 257: conflict-free col-strided reads

    const int q    = blockIdx.x;
    const int warp = threadIdx.x >> 5, lane = threadIdx.x & 31;
    const int gid = lane >> 2, tig = lane & 3;
    const int g = warp;

    const float* wg = g_w + (size_t)q * N_TOTAL + g * 4096;  // [e][d] 64x64
    const float* xq = x + (size_t)q * (P_DIM * C_DIM) + g * 64;

    float acc[2][8][4];
#pragma unroll
    for (int i = 0; i < 2; i++)
#pragma unroll
        for (int j = 0; j < 8; j++)
#pragma unroll
            for (int k = 0; k < 4; k++) acc[i][j][k] = 0.f;

#pragma unroll
    for (int ks = 0; ks < 8; ks++) {
        const int d0 = ks * 8 + tig;
        uint32_t a[2][4];
#pragma unroll
        for (int mt = 0; mt < 2; mt++) {
            int p = mt * 16 + gid;
            a[mt][0] = f2tf32(xq[p * C_DIM + d0]);
            a[mt][1] = f2tf32(xq[(p + 8) * C_DIM + d0]);
            a[mt][2] = f2tf32(xq[p * C_DIM + d0 + 4]);
            a[mt][3] = f2tf32(xq[(p + 8) * C_DIM + d0 + 4]);
        }
#pragma unroll
        for (int nt = 0; nt < 8; nt++) {
            int e = nt * 8 + gid;
            uint32_t b[2];
            b[0] = f2tf32(wg[e * 64 + d0]);
            b[1] = f2tf32(wg[e * 64 + d0 + 4]);
            mma_tf32(acc[0][nt], a[0], b);
            mma_tf32(acc[1][nt], a[1], b);
        }
    }

    // stash mixed tile in smem
#pragma unroll
    for (int mt = 0; mt < 2; mt++)
#pragma unroll
        for (int nt = 0; nt < 8; nt++) {
            int p = mt * 16 + gid;
            int c = g * 64 + nt * 8 + 2 * tig;
            sMix[p][c]     = acc[mt][nt][0];
            sMix[p][c + 1] = acc[mt][nt][1];
            sMix[p + 8][c]     = acc[mt][nt][2];
            sMix[p + 8][c + 1] = acc[mt][nt][3];
        }
    __syncthreads();

    // LayerNorm + ReLU: warp handles rows [warp*8, warp*8+8)
    float gm[8], bt[8];
#pragma unroll
    for (int j = 0; j < 8; j++) {
        int c = j * 32 + lane;
        gm[j] = gamma[c];
        bt[j] = beta[c];
    }
#pragma unroll
    for (int r = 0; r < 8; r++) {
        const int p = warp * 8 + r;
        float v[8], s = 0.f, s2 = 0.f;
#pragma unroll
        for (int j = 0; j < 8; j++) {
            v[j] = sMix[p][j * 32 + lane];
            s += v[j];
            s2 += v[j] * v[j];
        }
#pragma unroll
        for (int o = 16; o > 0; o >>= 1) {
            s  += __shfl_xor_sync(0xffffffffu, s, o);
            s2 += __shfl_xor_sync(0xffffffffu, s2, o);
        }
        const float mean = s * (1.f / 256.f);
        const float var  = s2 * (1.f / 256.f) - mean * mean;
        const float rs   = rsqrtf(var + 1e-5f);
        float* orow = out + (size_t)q * (P_DIM * C_DIM) + p * C_DIM;
#pragma unroll
        for (int j = 0; j < 8; j++) {
            float o = (v[j] - mean) * rs * gm[j] + bt[j];
            orow[j * 32 + lane] = fmaxf(o, 0.f);
        }
    }
}

// ---------------------------------------------------------------------------
extern "C" void kernel_launch(void* const* d_in, const int* in_sizes, int n_in,
                              void* d_out, int out_size) {
    const float* x     = (const float*)d_in[0];
    const float* qc    = (const float*)d_in[1];
    const float* Wg    = (const float*)d_in[2];
    const float* bg    = (const float*)d_in[3];
    const float* gamma = (const float*)d_in[4];
    const float* beta  = (const float*)d_in[5];
    float* out = (float*)d_out;

    dim3 gridA(N_TOTAL / BN, (M_TOTAL + BM - 1) / BM);  // 128 x 19
    gemm1_kernel<<<gridA, 256>>>(qc, Wg, bg);
    mix_ln_kernel<<<M_TOTAL, 128>>>(x, gamma, beta, out);
}